// round 1
// baseline (speedup 1.0000x reference)
#include <cuda_runtime.h>
#include <cuda_bf16.h>
#include <cstdint>

#define NN 50000
#define EE 600000
#define GG 512
#define HH 128

// ---------------- scratch (device globals; no allocation allowed) -------------
__device__ float    g_dinv[NN];          // deg -> dinv
__device__ float    g_h   [NN * HH];     // GEMM output buffer
__device__ float    g_agg [NN * HH];     // aggregation / layer output buffer
__device__ float    g_gate[NN];
__device__ float    g_expa[NN];
__device__ unsigned g_gmax[GG];
__device__ float    g_denom[GG];
__device__ float    g_pooled[GG * HH];

// ---------------- helpers ----------------
__device__ __forceinline__ unsigned fkey(float f) {
    unsigned b = __float_as_uint(f);
    return (b & 0x80000000u) ? ~b : (b | 0x80000000u);
}
__device__ __forceinline__ float fdec(unsigned u) {
    unsigned b = (u & 0x80000000u) ? (u & 0x7FFFFFFFu) : ~u;
    return __uint_as_float(b);
}

// ---------------- init: deg=1 (self loop), gmax/denom/pooled = 0 --------------
__global__ void k_init() {
    int i = blockIdx.x * blockDim.x + threadIdx.x;
    if (i < NN) g_dinv[i] = 1.0f;                 // self-loop contribution to deg
    if (i < GG) { g_gmax[i] = 0u; g_denom[i] = 0.0f; }
    if (i < GG * HH) g_pooled[i] = 0.0f;
}

// deg accumulation over dst
__global__ void k_deg(const int* __restrict__ ei) {
    int i = blockIdx.x * blockDim.x + threadIdx.x;
    if (i < EE) atomicAdd(&g_dinv[ei[EE + i]], 1.0f);
}

__global__ void k_dinv_fin() {
    int i = blockIdx.x * blockDim.x + threadIdx.x;
    if (i < NN) g_dinv[i] = rsqrtf(g_dinv[i]);    // deg >= 1 always (self loop)
}

// ---------------- GEMM: Y[n,128] = X[n,128] @ W[128,128] (+bias)(+relu) ------
// 256 threads, 64x128 tile, each thread 4 rows x 8 cols.
__global__ void k_gemm(const float* __restrict__ X, const float* __restrict__ W,
                       const float* __restrict__ bias, float* __restrict__ Y,
                       int n, int do_relu) {
    __shared__ float Xs[64][33];
    __shared__ float Ws[32][128];
    const int tid = threadIdx.x;
    const int tx = tid & 15;      // col group (8 cols each)
    const int ty = tid >> 4;      // row group (4 rows each)
    const int row0 = blockIdx.x * 64;

    float acc[4][8];
#pragma unroll
    for (int r = 0; r < 4; r++)
#pragma unroll
        for (int c = 0; c < 8; c++) acc[r][c] = 0.0f;

    for (int k0 = 0; k0 < 128; k0 += 32) {
        // load X tile: 64x32 = 512 float4
#pragma unroll
        for (int it = 0; it < 2; it++) {
            int slot = tid + it * 256;        // 0..511
            int r = slot >> 3;                // row 0..63
            int c4 = slot & 7;                // float4 idx in 32-col chunk
            int gr = row0 + r;
            float4 v = make_float4(0.f, 0.f, 0.f, 0.f);
            if (gr < n) v = ((const float4*)(X + (size_t)gr * 128 + k0))[c4];
            Xs[r][c4 * 4 + 0] = v.x; Xs[r][c4 * 4 + 1] = v.y;
            Xs[r][c4 * 4 + 2] = v.z; Xs[r][c4 * 4 + 3] = v.w;
        }
        // load W tile: 32x128 = 1024 float4
#pragma unroll
        for (int it = 0; it < 4; it++) {
            int slot = tid + it * 256;        // 0..1023
            int r = slot >> 5;                // k row 0..31
            int c4 = slot & 31;
            float4 v = ((const float4*)(W + (size_t)(k0 + r) * 128))[c4];
            *((float4*)&Ws[r][c4 * 4]) = v;
        }
        __syncthreads();
#pragma unroll
        for (int kk = 0; kk < 32; kk++) {
            const float4 w0 = *(const float4*)&Ws[kk][tx * 8];
            const float4 w1 = *(const float4*)&Ws[kk][tx * 8 + 4];
#pragma unroll
            for (int r = 0; r < 4; r++) {
                float xv = Xs[ty * 4 + r][kk];
                acc[r][0] += xv * w0.x; acc[r][1] += xv * w0.y;
                acc[r][2] += xv * w0.z; acc[r][3] += xv * w0.w;
                acc[r][4] += xv * w1.x; acc[r][5] += xv * w1.y;
                acc[r][6] += xv * w1.z; acc[r][7] += xv * w1.w;
            }
        }
        __syncthreads();
    }
    float b[8];
#pragma unroll
    for (int c = 0; c < 8; c++) b[c] = bias ? bias[tx * 8 + c] : 0.0f;
#pragma unroll
    for (int r = 0; r < 4; r++) {
        int gr = row0 + ty * 4 + r;
        if (gr >= n) break;
        float4 o0, o1;
        o0.x = acc[r][0] + b[0]; o0.y = acc[r][1] + b[1];
        o0.z = acc[r][2] + b[2]; o0.w = acc[r][3] + b[3];
        o1.x = acc[r][4] + b[4]; o1.y = acc[r][5] + b[5];
        o1.z = acc[r][6] + b[6]; o1.w = acc[r][7] + b[7];
        if (do_relu) {
            o0.x = fmaxf(o0.x, 0.f); o0.y = fmaxf(o0.y, 0.f);
            o0.z = fmaxf(o0.z, 0.f); o0.w = fmaxf(o0.w, 0.f);
            o1.x = fmaxf(o1.x, 0.f); o1.y = fmaxf(o1.y, 0.f);
            o1.z = fmaxf(o1.z, 0.f); o1.w = fmaxf(o1.w, 0.f);
        }
        ((float4*)(Y + (size_t)gr * 128 + tx * 8))[0] = o0;
        ((float4*)(Y + (size_t)gr * 128 + tx * 8))[1] = o1;
    }
}

// ---------------- agg init: agg = bias + h * dinv^2 (self loop) ---------------
__global__ void k_agg_init(const float* __restrict__ h, const float* __restrict__ bias,
                           float* __restrict__ agg) {
    int idx = blockIdx.x * blockDim.x + threadIdx.x;   // float4 units, NN*32
    if (idx >= NN * 32) return;
    int node = idx >> 5;
    int c4 = idx & 31;
    float di = g_dinv[node];
    float w = di * di;
    float4 hv = ((const float4*)h)[idx];
    float4 bv = ((const float4*)bias)[c4];
    float4 o;
    o.x = bv.x + hv.x * w; o.y = bv.y + hv.y * w;
    o.z = bv.z + hv.z * w; o.w = bv.w + hv.w * w;
    ((float4*)agg)[idx] = o;
}

// ---------------- edge scatter: agg[d] += h[s] * dinv[s]*dinv[d] --------------
// one warp per edge, lane handles one float4 (4 cols), vector reduction
__global__ void k_scatter(const int* __restrict__ ei, const float* __restrict__ h,
                          float* __restrict__ agg) {
    int wid = (blockIdx.x * blockDim.x + threadIdx.x) >> 5;
    int lane = threadIdx.x & 31;
    if (wid >= EE) return;
    int s = ei[wid];
    int d = ei[EE + wid];
    float w = g_dinv[s] * g_dinv[d];
    float4 v = ((const float4*)(h + (size_t)s * 128))[lane];
    v.x *= w; v.y *= w; v.z *= w; v.w *= w;
    float* p = agg + (size_t)d * 128 + lane * 4;
    asm volatile("red.global.add.v4.f32 [%0], {%1,%2,%3,%4};"
                 :: "l"(p), "f"(v.x), "f"(v.y), "f"(v.z), "f"(v.w) : "memory");
}

// ---------------- LayerNorm + ReLU in place (warp per node) -------------------
__global__ void k_ln_relu(float* __restrict__ hio, const float* __restrict__ gamma,
                          const float* __restrict__ beta) {
    int wid = (blockIdx.x * blockDim.x + threadIdx.x) >> 5;
    int lane = threadIdx.x & 31;
    if (wid >= NN) return;
    float4 v = ((const float4*)(hio + (size_t)wid * 128))[lane];
    float s = v.x + v.y + v.z + v.w;
#pragma unroll
    for (int off = 16; off; off >>= 1) s += __shfl_xor_sync(0xFFFFFFFFu, s, off);
    float m = s * (1.0f / 128.0f);
    float dx = v.x - m, dy = v.y - m, dz = v.z - m, dw = v.w - m;
    float q = dx * dx + dy * dy + dz * dz + dw * dw;
#pragma unroll
    for (int off = 16; off; off >>= 1) q += __shfl_xor_sync(0xFFFFFFFFu, q, off);
    float rinv = rsqrtf(q * (1.0f / 128.0f) + 1e-5f);
    float4 gv = ((const float4*)gamma)[lane];
    float4 bv = ((const float4*)beta)[lane];
    float4 o;
    o.x = fmaxf(dx * rinv * gv.x + bv.x, 0.f);
    o.y = fmaxf(dy * rinv * gv.y + bv.y, 0.f);
    o.z = fmaxf(dz * rinv * gv.z + bv.z, 0.f);
    o.w = fmaxf(dw * rinv * gv.w + bv.w, 0.f);
    ((float4*)(hio + (size_t)wid * 128))[lane] = o;
}

// ---------------- gate reduce: gate[i] = ghid[i] . gw2 + gb2; segment max -----
__global__ void k_gate(const float* __restrict__ ghid, const float* __restrict__ gw2,
                       const float* __restrict__ gb2, const int* __restrict__ batch) {
    int wid = (blockIdx.x * blockDim.x + threadIdx.x) >> 5;
    int lane = threadIdx.x & 31;
    if (wid >= NN) return;
    float4 hv = ((const float4*)(ghid + (size_t)wid * 128))[lane];
    float4 wv = ((const float4*)gw2)[lane];
    float s = hv.x * wv.x + hv.y * wv.y + hv.z * wv.z + hv.w * wv.w;
#pragma unroll
    for (int off = 16; off; off >>= 1) s += __shfl_xor_sync(0xFFFFFFFFu, s, off);
    if (lane == 0) {
        float gt = s + gb2[0];
        g_gate[wid] = gt;
        atomicMax(&g_gmax[batch[wid]], fkey(gt));
    }
}

// ---------------- exp & denom -------------------------------------------------
__global__ void k_exp(const int* __restrict__ batch) {
    int i = blockIdx.x * blockDim.x + threadIdx.x;
    if (i >= NN) return;
    int g = batch[i];
    float a = expf(g_gate[i] - fdec(g_gmax[g]));
    g_expa[i] = a;
    atomicAdd(&g_denom[g], a);
}

// ---------------- pooled += alpha * h (warp per node) -------------------------
__global__ void k_pool(const float* __restrict__ h, const int* __restrict__ batch) {
    int wid = (blockIdx.x * blockDim.x + threadIdx.x) >> 5;
    int lane = threadIdx.x & 31;
    if (wid >= NN) return;
    int g = batch[wid];
    float alpha = g_expa[wid] / g_denom[g];
    float4 v = ((const float4*)(h + (size_t)wid * 128))[lane];
    v.x *= alpha; v.y *= alpha; v.z *= alpha; v.w *= alpha;
    float* p = g_pooled + (size_t)g * 128 + lane * 4;
    asm volatile("red.global.add.v4.f32 [%0], {%1,%2,%3,%4};"
                 :: "l"(p), "f"(v.x), "f"(v.y), "f"(v.z), "f"(v.w) : "memory");
}

// ---------------- classifier: block per graph ---------------------------------
__global__ void k_cls(const float* __restrict__ cw1, const float* __restrict__ cb1,
                      const float* __restrict__ cw2, const float* __restrict__ cb2,
                      float* __restrict__ out) {
    __shared__ float p[128];
    __shared__ float s0[128];
    __shared__ float s1[128];
    int g = blockIdx.x;
    int t = threadIdx.x;
    p[t] = g_pooled[(size_t)g * 128 + t];
    __syncthreads();
    float acc = cb1[t];
#pragma unroll 8
    for (int k = 0; k < 128; k++) acc += p[k] * cw1[k * 128 + t];
    acc = fmaxf(acc, 0.0f);
    s0[t] = acc * cw2[t * 2 + 0];
    s1[t] = acc * cw2[t * 2 + 1];
    __syncthreads();
    for (int off = 64; off; off >>= 1) {
        if (t < off) { s0[t] += s0[t + off]; s1[t] += s1[t + off]; }
        __syncthreads();
    }
    if (t == 0) {
        out[g * 2 + 0] = s0[0] + cb2[0];
        out[g * 2 + 1] = s1[0] + cb2[1];
    }
}

// ---------------- launch ------------------------------------------------------
extern "C" void kernel_launch(void* const* d_in, const int* in_sizes, int n_in,
                              void* d_out, int out_size) {
    const float* x      = (const float*)d_in[0];
    const int*   ei     = (const int*)  d_in[1];
    const int*   batch  = (const int*)  d_in[2];
    const float* W1     = (const float*)d_in[3];
    const float* b1     = (const float*)d_in[4];
    const float* ln1g   = (const float*)d_in[5];
    const float* ln1b   = (const float*)d_in[6];
    const float* W2     = (const float*)d_in[7];
    const float* b2     = (const float*)d_in[8];
    const float* ln2g   = (const float*)d_in[9];
    const float* ln2b   = (const float*)d_in[10];
    const float* gw1    = (const float*)d_in[11];
    const float* gb1    = (const float*)d_in[12];
    const float* gw2    = (const float*)d_in[13];
    const float* gb2    = (const float*)d_in[14];
    const float* cw1    = (const float*)d_in[15];
    const float* cb1    = (const float*)d_in[16];
    const float* cw2    = (const float*)d_in[17];
    const float* cb2    = (const float*)d_in[18];
    float* out = (float*)d_out;

    float* hbuf;   cudaGetSymbolAddress((void**)&hbuf, g_h);
    float* abuf;   cudaGetSymbolAddress((void**)&abuf, g_agg);

    const int T = 256;
    // init (covers NN, GG, GG*HH=65536)
    k_init<<<(GG * HH + T - 1) / T, T>>>();
    k_deg<<<(EE + T - 1) / T, T>>>(ei);
    k_dinv_fin<<<(NN + T - 1) / T, T>>>();

    int gemm_blocks = (NN + 63) / 64;
    int warp_blocks = (NN * 32 + T - 1) / T;   // warp-per-node kernels
    int edge_blocks = (EE * 32 + T - 1) / T;   // warp-per-edge
    int f4_blocks   = (NN * 32 + T - 1) / T;   // float4-per-thread over N*H

    // ---- layer 1 ----
    k_gemm<<<gemm_blocks, T>>>(x, W1, nullptr, hbuf, NN, 0);
    k_agg_init<<<f4_blocks, T>>>(hbuf, b1, abuf);
    k_scatter<<<edge_blocks, T>>>(ei, hbuf, abuf);
    k_ln_relu<<<warp_blocks, T>>>(abuf, ln1g, ln1b);

    // ---- layer 2 ----
    k_gemm<<<gemm_blocks, T>>>(abuf, W2, nullptr, hbuf, NN, 0);
    k_agg_init<<<f4_blocks, T>>>(hbuf, b2, abuf);   // safe: gemm already consumed abuf
    k_scatter<<<edge_blocks, T>>>(ei, hbuf, abuf);
    k_ln_relu<<<warp_blocks, T>>>(abuf, ln2g, ln2b);

    // ---- attention pooling ----
    k_gemm<<<gemm_blocks, T>>>(abuf, gw1, gb1, hbuf, NN, 1);   // gate hidden (relu)
    k_gate<<<warp_blocks, T>>>(hbuf, gw2, gb2, batch);
    k_exp<<<(NN + T - 1) / T, T>>>(batch);
    k_pool<<<warp_blocks, T>>>(abuf, batch);

    // ---- classifier ----
    k_cls<<<GG, 128>>>(cw1, cb1, cw2, cb2, out);
}

// round 3
// speedup vs baseline: 1.2047x; 1.2047x over previous
#include <cuda_runtime.h>
#include <cuda_bf16.h>
#include <cstdint>

#define NN 50000
#define EE 600000
#define GG 512
#define HH 128

// ---------------- scratch (device globals; no allocation allowed) -------------
__device__ float    g_dinv[NN];
__device__ float    g_h   [NN * HH];
__device__ float    g_agg [NN * HH];
__device__ float    g_gate[NN];
__device__ float    g_expa[NN];
__device__ unsigned g_gmax[GG];
__device__ float    g_denom[GG];
__device__ float    g_pooled[GG * HH];

// ---------------- helpers ----------------
__device__ __forceinline__ unsigned fkey(float f) {
    unsigned b = __float_as_uint(f);
    return (b & 0x80000000u) ? ~b : (b | 0x80000000u);
}
__device__ __forceinline__ float fdec(unsigned u) {
    unsigned b = (u & 0x80000000u) ? (u & 0x7FFFFFFFu) : ~u;
    return __uint_as_float(b);
}

// packed f32x2 helpers (base sm_100+ ISA; FFMA2 in SASS)
__device__ __forceinline__ unsigned long long dup_f32x2(float x) {
    unsigned long long r;
    asm("mov.b64 %0, {%1, %1};" : "=l"(r) : "r"(__float_as_uint(x)));
    return r;
}
__device__ __forceinline__ unsigned long long pack_f32x2(float lo, float hi) {
    unsigned long long r;
    asm("mov.b64 %0, {%1, %2};" : "=l"(r)
        : "r"(__float_as_uint(lo)), "r"(__float_as_uint(hi)));
    return r;
}
__device__ __forceinline__ void fma_f32x2(unsigned long long& d,
                                          unsigned long long a,
                                          unsigned long long b) {
    asm("fma.rn.f32x2 %0, %1, %2, %0;" : "+l"(d) : "l"(a), "l"(b));
}
__device__ __forceinline__ float lo_f(unsigned long long v) {
    return __uint_as_float((unsigned)(v & 0xFFFFFFFFull));
}
__device__ __forceinline__ float hi_f(unsigned long long v) {
    return __uint_as_float((unsigned)(v >> 32));
}

// ---------------- GEMM: Y[n,128] = X[n,128] @ W[128,128]  (FFMA2, 8x8 blocking)
// 256 threads, 128x128 tile, K-chunks of 32. X stored K-transposed in smem.
// Epilogue modes:
//   AGG != null (layers): Y = acc ; AGG = agg_bias + acc * dinv[row]^2
//   AGG == null (gate)  : Y = relu(acc + bias_out)
__global__ void __launch_bounds__(256, 2)
k_gemm2(const float* __restrict__ X, const float* __restrict__ W,
        const float* __restrict__ bias_out, const float* __restrict__ agg_bias,
        float* __restrict__ Y, float* __restrict__ AGG, int n) {
    __shared__ float XsT[32][132];   // [k][row]
    __shared__ float Ws[32][132];    // [k][col]

    const int tid = threadIdx.x;
    const int tx = tid & 15;          // col group (8 cols)
    const int ty = tid >> 4;          // row group (8 rows)
    const int tx8 = tx * 8, ty8 = ty * 8;
    const int row0 = blockIdx.x * 128;

    unsigned long long acc[8][4];
#pragma unroll
    for (int r = 0; r < 8; r++)
#pragma unroll
        for (int c = 0; c < 4; c++) acc[r][c] = 0ull;

    for (int k0 = 0; k0 < 128; k0 += 32) {
        // load X tile (128 rows x 32 cols) -> transposed XsT[k][row]
#pragma unroll
        for (int it = 0; it < 4; it++) {
            int s = tid + it * 256;           // 0..1023
            int r = s >> 3;                   // row 0..127
            int c4 = s & 7;                   // float4 within 32-col chunk
            int gr = row0 + r;
            float4 v = make_float4(0.f, 0.f, 0.f, 0.f);
            if (gr < n) v = ((const float4*)(X + (size_t)gr * 128 + k0))[c4];
            XsT[c4 * 4 + 0][r] = v.x;
            XsT[c4 * 4 + 1][r] = v.y;
            XsT[c4 * 4 + 2][r] = v.z;
            XsT[c4 * 4 + 3][r] = v.w;
        }
        // load W tile (32 rows x 128 cols)
#pragma unroll
        for (int it = 0; it < 4; it++) {
            int s = tid + it * 256;
            int r = s >> 5;                   // k 0..31
            int c4 = s & 31;
            float4 v = ((const float4*)(W + (size_t)(k0 + r) * 128))[c4];
            *(float4*)&Ws[r][c4 * 4] = v;
        }
        __syncthreads();

#pragma unroll 4
        for (int kk = 0; kk < 32; kk++) {
            float4 xa = *(const float4*)&XsT[kk][ty8];
            float4 xb = *(const float4*)&XsT[kk][ty8 + 4];
            float4 wa = *(const float4*)&Ws[kk][tx8];
            float4 wb = *(const float4*)&Ws[kk][tx8 + 4];
            unsigned long long wp[4];
            wp[0] = pack_f32x2(wa.x, wa.y);
            wp[1] = pack_f32x2(wa.z, wa.w);
            wp[2] = pack_f32x2(wb.x, wb.y);
            wp[3] = pack_f32x2(wb.z, wb.w);
            unsigned long long xp[8];
            xp[0] = dup_f32x2(xa.x); xp[1] = dup_f32x2(xa.y);
            xp[2] = dup_f32x2(xa.z); xp[3] = dup_f32x2(xa.w);
            xp[4] = dup_f32x2(xb.x); xp[5] = dup_f32x2(xb.y);
            xp[6] = dup_f32x2(xb.z); xp[7] = dup_f32x2(xb.w);
#pragma unroll
            for (int r = 0; r < 8; r++)
#pragma unroll
                for (int c = 0; c < 4; c++) fma_f32x2(acc[r][c], xp[r], wp[c]);
        }
        __syncthreads();
    }

    // epilogue
    float bout[8];
#pragma unroll
    for (int c = 0; c < 8; c++) bout[c] = bias_out ? bias_out[tx8 + c] : 0.0f;
    float abv[8];
    if (AGG) {
#pragma unroll
        for (int c = 0; c < 8; c++) abv[c] = agg_bias[tx8 + c];
    }

#pragma unroll
    for (int r = 0; r < 8; r++) {
        int row = row0 + ty8 + r;
        if (row >= n) break;
        float o[8];
        o[0] = lo_f(acc[r][0]); o[1] = hi_f(acc[r][0]);
        o[2] = lo_f(acc[r][1]); o[3] = hi_f(acc[r][1]);
        o[4] = lo_f(acc[r][2]); o[5] = hi_f(acc[r][2]);
        o[6] = lo_f(acc[r][3]); o[7] = hi_f(acc[r][3]);
        if (AGG) {
            float di = g_dinv[row];
            float w2 = di * di;
            float4 y0 = make_float4(o[0], o[1], o[2], o[3]);
            float4 y1 = make_float4(o[4], o[5], o[6], o[7]);
            *(float4*)(Y + (size_t)row * 128 + tx8)     = y0;
            *(float4*)(Y + (size_t)row * 128 + tx8 + 4) = y1;
            float4 a0, a1;
            a0.x = abv[0] + o[0] * w2; a0.y = abv[1] + o[1] * w2;
            a0.z = abv[2] + o[2] * w2; a0.w = abv[3] + o[3] * w2;
            a1.x = abv[4] + o[4] * w2; a1.y = abv[5] + o[5] * w2;
            a1.z = abv[6] + o[6] * w2; a1.w = abv[7] + o[7] * w2;
            *(float4*)(AGG + (size_t)row * 128 + tx8)     = a0;
            *(float4*)(AGG + (size_t)row * 128 + tx8 + 4) = a1;
        } else {
            float4 y0, y1;
            y0.x = fmaxf(o[0] + bout[0], 0.f); y0.y = fmaxf(o[1] + bout[1], 0.f);
            y0.z = fmaxf(o[2] + bout[2], 0.f); y0.w = fmaxf(o[3] + bout[3], 0.f);
            y1.x = fmaxf(o[4] + bout[4], 0.f); y1.y = fmaxf(o[5] + bout[5], 0.f);
            y1.z = fmaxf(o[6] + bout[6], 0.f); y1.w = fmaxf(o[7] + bout[7], 0.f);
            *(float4*)(Y + (size_t)row * 128 + tx8)     = y0;
            *(float4*)(Y + (size_t)row * 128 + tx8 + 4) = y1;
        }
    }
}

// ---------------- init ----------------
__global__ void k_init() {
    int i = blockIdx.x * blockDim.x + threadIdx.x;
    if (i < NN) g_dinv[i] = 1.0f;
    if (i < GG) { g_gmax[i] = 0u; g_denom[i] = 0.0f; }
    if (i < GG * HH) g_pooled[i] = 0.0f;
}

__global__ void k_deg(const int* __restrict__ ei) {
    int i = blockIdx.x * blockDim.x + threadIdx.x;
    if (i < EE) atomicAdd(&g_dinv[ei[EE + i]], 1.0f);
}

__global__ void k_dinv_fin() {
    int i = blockIdx.x * blockDim.x + threadIdx.x;
    if (i < NN) g_dinv[i] = rsqrtf(g_dinv[i]);
}

// ---------------- edge scatter: agg[d] += h[s] * dinv[s]*dinv[d] --------------
__global__ void k_scatter(const int* __restrict__ ei, const float* __restrict__ h,
                          float* __restrict__ agg) {
    int wid = (blockIdx.x * blockDim.x + threadIdx.x) >> 5;
    int lane = threadIdx.x & 31;
    if (wid >= EE) return;
    int s = ei[wid];
    int d = ei[EE + wid];
    float w = g_dinv[s] * g_dinv[d];
    float4 v = ((const float4*)(h + (size_t)s * 128))[lane];
    v.x *= w; v.y *= w; v.z *= w; v.w *= w;
    float* p = agg + (size_t)d * 128 + lane * 4;
    asm volatile("red.global.add.v4.f32 [%0], {%1,%2,%3,%4};"
                 :: "l"(p), "f"(v.x), "f"(v.y), "f"(v.z), "f"(v.w) : "memory");
}

// ---------------- LayerNorm + ReLU (warp per node) ----------------------------
__global__ void k_ln_relu(float* __restrict__ hio, const float* __restrict__ gamma,
                          const float* __restrict__ beta) {
    int wid = (blockIdx.x * blockDim.x + threadIdx.x) >> 5;
    int lane = threadIdx.x & 31;
    if (wid >= NN) return;
    float4 v = ((const float4*)(hio + (size_t)wid * 128))[lane];
    float s = v.x + v.y + v.z + v.w;
#pragma unroll
    for (int off = 16; off; off >>= 1) s += __shfl_xor_sync(0xFFFFFFFFu, s, off);
    float m = s * (1.0f / 128.0f);
    float dx = v.x - m, dy = v.y - m, dz = v.z - m, dw = v.w - m;
    float q = dx * dx + dy * dy + dz * dz + dw * dw;
#pragma unroll
    for (int off = 16; off; off >>= 1) q += __shfl_xor_sync(0xFFFFFFFFu, q, off);
    float rinv = rsqrtf(q * (1.0f / 128.0f) + 1e-5f);
    float4 gv = ((const float4*)gamma)[lane];
    float4 bv = ((const float4*)beta)[lane];
    float4 o;
    o.x = fmaxf(dx * rinv * gv.x + bv.x, 0.f);
    o.y = fmaxf(dy * rinv * gv.y + bv.y, 0.f);
    o.z = fmaxf(dz * rinv * gv.z + bv.z, 0.f);
    o.w = fmaxf(dw * rinv * gv.w + bv.w, 0.f);
    ((float4*)(hio + (size_t)wid * 128))[lane] = o;
}

// ---------------- gate reduce -------------------------------------------------
__global__ void k_gate(const float* __restrict__ ghid, const float* __restrict__ gw2,
                       const float* __restrict__ gb2, const int* __restrict__ batch) {
    int wid = (blockIdx.x * blockDim.x + threadIdx.x) >> 5;
    int lane = threadIdx.x & 31;
    if (wid >= NN) return;
    float4 hv = ((const float4*)(ghid + (size_t)wid * 128))[lane];
    float4 wv = ((const float4*)gw2)[lane];
    float s = hv.x * wv.x + hv.y * wv.y + hv.z * wv.z + hv.w * wv.w;
#pragma unroll
    for (int off = 16; off; off >>= 1) s += __shfl_xor_sync(0xFFFFFFFFu, s, off);
    if (lane == 0) {
        float gt = s + gb2[0];
        g_gate[wid] = gt;
        atomicMax(&g_gmax[batch[wid]], fkey(gt));
    }
}

__global__ void k_exp(const int* __restrict__ batch) {
    int i = blockIdx.x * blockDim.x + threadIdx.x;
    if (i >= NN) return;
    int g = batch[i];
    float a = expf(g_gate[i] - fdec(g_gmax[g]));
    g_expa[i] = a;
    atomicAdd(&g_denom[g], a);
}

__global__ void k_pool(const float* __restrict__ h, const int* __restrict__ batch) {
    int wid = (blockIdx.x * blockDim.x + threadIdx.x) >> 5;
    int lane = threadIdx.x & 31;
    if (wid >= NN) return;
    int g = batch[wid];
    float alpha = g_expa[wid] / g_denom[g];
    float4 v = ((const float4*)(h + (size_t)wid * 128))[lane];
    v.x *= alpha; v.y *= alpha; v.z *= alpha; v.w *= alpha;
    float* p = g_pooled + (size_t)g * 128 + lane * 4;
    asm volatile("red.global.add.v4.f32 [%0], {%1,%2,%3,%4};"
                 :: "l"(p), "f"(v.x), "f"(v.y), "f"(v.z), "f"(v.w) : "memory");
}

// ---------------- classifier --------------------------------------------------
__global__ void k_cls(const float* __restrict__ cw1, const float* __restrict__ cb1,
                      const float* __restrict__ cw2, const float* __restrict__ cb2,
                      float* __restrict__ out) {
    __shared__ float p[128];
    __shared__ float s0[128];
    __shared__ float s1[128];
    int g = blockIdx.x;
    int t = threadIdx.x;
    p[t] = g_pooled[(size_t)g * 128 + t];
    __syncthreads();
    float acc = cb1[t];
#pragma unroll 8
    for (int k = 0; k < 128; k++) acc += p[k] * cw1[k * 128 + t];
    acc = fmaxf(acc, 0.0f);
    s0[t] = acc * cw2[t * 2 + 0];
    s1[t] = acc * cw2[t * 2 + 1];
    __syncthreads();
    for (int off = 64; off; off >>= 1) {
        if (t < off) { s0[t] += s0[t + off]; s1[t] += s1[t + off]; }
        __syncthreads();
    }
    if (t == 0) {
        out[g * 2 + 0] = s0[0] + cb2[0];
        out[g * 2 + 1] = s1[0] + cb2[1];
    }
}

// ---------------- launch ------------------------------------------------------
extern "C" void kernel_launch(void* const* d_in, const int* in_sizes, int n_in,
                              void* d_out, int out_size) {
    const float* x      = (const float*)d_in[0];
    const int*   ei     = (const int*)  d_in[1];
    const int*   batch  = (const int*)  d_in[2];
    const float* W1     = (const float*)d_in[3];
    const float* b1     = (const float*)d_in[4];
    const float* ln1g   = (const float*)d_in[5];
    const float* ln1b   = (const float*)d_in[6];
    const float* W2     = (const float*)d_in[7];
    const float* b2     = (const float*)d_in[8];
    const float* ln2g   = (const float*)d_in[9];
    const float* ln2b   = (const float*)d_in[10];
    const float* gw1    = (const float*)d_in[11];
    const float* gb1    = (const float*)d_in[12];
    const float* gw2    = (const float*)d_in[13];
    const float* gb2    = (const float*)d_in[14];
    const float* cw1    = (const float*)d_in[15];
    const float* cb1    = (const float*)d_in[16];
    const float* cw2    = (const float*)d_in[17];
    const float* cb2    = (const float*)d_in[18];
    float* out = (float*)d_out;

    float* hbuf;   cudaGetSymbolAddress((void**)&hbuf, g_h);
    float* abuf;   cudaGetSymbolAddress((void**)&abuf, g_agg);

    const int T = 256;
    k_init<<<(GG * HH + T - 1) / T, T>>>();
    k_deg<<<(EE + T - 1) / T, T>>>(ei);
    k_dinv_fin<<<(NN + T - 1) / T, T>>>();

    int gemm_blocks = (NN + 127) / 128;        // 391
    int warp_blocks = (NN * 32 + T - 1) / T;
    int edge_blocks = (EE * 32 + T - 1) / T;

    // ---- layer 1 ----  (gemm fuses agg init: agg = b1 + h*dinv^2)
    k_gemm2<<<gemm_blocks, T>>>(x, W1, nullptr, b1, hbuf, abuf, NN);
    k_scatter<<<edge_blocks, T>>>(ei, hbuf, abuf);
    k_ln_relu<<<warp_blocks, T>>>(abuf, ln1g, ln1b);

    // ---- layer 2 ----
    k_gemm2<<<gemm_blocks, T>>>(abuf, W2, nullptr, b2, hbuf, abuf, NN);
    k_scatter<<<edge_blocks, T>>>(ei, hbuf, abuf);
    k_ln_relu<<<warp_blocks, T>>>(abuf, ln2g, ln2b);

    // ---- attention pooling ----
    k_gemm2<<<gemm_blocks, T>>>(abuf, gw1, gb1, nullptr, hbuf, nullptr, NN);
    k_gate<<<warp_blocks, T>>>(hbuf, gw2, gb2, batch);
    k_exp<<<(NN + T - 1) / T, T>>>(batch);
    k_pool<<<warp_blocks, T>>>(abuf, batch);

    // ---- classifier ----
    k_cls<<<GG, 128>>>(cw1, cb1, cw2, cb2, out);
}

// round 5
// speedup vs baseline: 1.5843x; 1.3151x over previous
#include <cuda_runtime.h>
#include <cuda_bf16.h>
#include <cstdint>

#define NN 50000
#define EE 600000
#define GG 512
#define HH 128
#define NB 196          // scan blocks = ceil(NN/256)

// ---------------- scratch (device globals; no allocation allowed) -------------
__device__ float    g_dinv[NN];
__device__ int      g_cnt[NN];
__device__ int      g_off[NN + 1];
__device__ int      g_pos[NN];
__device__ int      g_bsum[256];
__device__ int      g_boff[256];
__device__ int      g_csr[EE];
__device__ float    g_h   [NN * HH];
__device__ float    g_agg [NN * HH];
__device__ float    g_gate[NN];
__device__ float    g_expa[NN];
__device__ unsigned g_gmax[GG];
__device__ float    g_denom[GG];
__device__ float    g_pooled[GG * HH];

// ---------------- helpers ----------------
__device__ __forceinline__ unsigned fkey(float f) {
    unsigned b = __float_as_uint(f);
    return (b & 0x80000000u) ? ~b : (b | 0x80000000u);
}
__device__ __forceinline__ float fdec(unsigned u) {
    unsigned b = (u & 0x80000000u) ? (u & 0x7FFFFFFFu) : ~u;
    return __uint_as_float(b);
}

// packed f32x2 helpers (base sm_100+ ISA; FFMA2 in SASS)
__device__ __forceinline__ unsigned long long dup_f32x2(float x) {
    unsigned long long r;
    asm("mov.b64 %0, {%1, %1};" : "=l"(r) : "r"(__float_as_uint(x)));
    return r;
}
__device__ __forceinline__ void fma_f32x2(unsigned long long& d,
                                          unsigned long long a,
                                          unsigned long long b) {
    asm("fma.rn.f32x2 %0, %1, %2, %0;" : "+l"(d) : "l"(a), "l"(b));
}
__device__ __forceinline__ float lo_f(unsigned long long v) {
    return __uint_as_float((unsigned)(v & 0xFFFFFFFFull));
}
__device__ __forceinline__ float hi_f(unsigned long long v) {
    return __uint_as_float((unsigned)(v >> 32));
}

// ---------------- GEMM: acc[n,128] = X[n,128] @ W[128,128]  (FFMA2, 8x8) ------
// Modes:
//   AGG != null : Y = acc ; AGG = agg_bias + acc * dinv[row]^2   (layer mode)
//   GW2 != null : gate mode — no Y write; per-row gate = relu(acc+bias_out).GW2
//                 reduced across 16 lanes, written to g_gate + segment max.
__global__ void __launch_bounds__(256, 2)
k_gemm2(const float* __restrict__ X, const float* __restrict__ W,
        const float* __restrict__ bias_out, const float* __restrict__ agg_bias,
        float* __restrict__ Y, float* __restrict__ AGG,
        const float* __restrict__ GW2, const float* __restrict__ gb2,
        const int* __restrict__ batch, int n) {
    __shared__ float XsT[32][132];   // [k][row]
    __shared__ float Ws[32][132];    // [k][col]

    const int tid = threadIdx.x;
    const int tx = tid & 15;          // col group (8 cols)
    const int ty = tid >> 4;          // row group (8 rows)
    const int tx8 = tx * 8, ty8 = ty * 8;
    const int row0 = blockIdx.x * 128;

    unsigned long long acc[8][4];
#pragma unroll
    for (int r = 0; r < 8; r++)
#pragma unroll
        for (int c = 0; c < 4; c++) acc[r][c] = 0ull;

    for (int k0 = 0; k0 < 128; k0 += 32) {
        // load X tile (128 rows x 32 cols) -> transposed XsT[k][row]
#pragma unroll
        for (int it = 0; it < 4; it++) {
            int s = tid + it * 256;
            int r = s >> 3;
            int c4 = s & 7;
            int gr = row0 + r;
            float4 v = make_float4(0.f, 0.f, 0.f, 0.f);
            if (gr < n) v = ((const float4*)(X + (size_t)gr * 128 + k0))[c4];
            XsT[c4 * 4 + 0][r] = v.x;
            XsT[c4 * 4 + 1][r] = v.y;
            XsT[c4 * 4 + 2][r] = v.z;
            XsT[c4 * 4 + 3][r] = v.w;
        }
        // load W tile (32 rows x 128 cols)
#pragma unroll
        for (int it = 0; it < 4; it++) {
            int s = tid + it * 256;
            int r = s >> 5;
            int c4 = s & 31;
            float4 v = ((const float4*)(W + (size_t)(k0 + r) * 128))[c4];
            *(float4*)&Ws[r][c4 * 4] = v;
        }
        __syncthreads();

#pragma unroll 4
        for (int kk = 0; kk < 32; kk++) {
            // W pairs loaded directly as aligned 64-bit pairs (no packing movs)
            ulonglong2 w01 = *(const ulonglong2*)&Ws[kk][tx8];
            ulonglong2 w23 = *(const ulonglong2*)&Ws[kk][tx8 + 4];
            float4 xa = *(const float4*)&XsT[kk][ty8];
            float4 xb = *(const float4*)&XsT[kk][ty8 + 4];
            unsigned long long xp[8];
            xp[0] = dup_f32x2(xa.x); xp[1] = dup_f32x2(xa.y);
            xp[2] = dup_f32x2(xa.z); xp[3] = dup_f32x2(xa.w);
            xp[4] = dup_f32x2(xb.x); xp[5] = dup_f32x2(xb.y);
            xp[6] = dup_f32x2(xb.z); xp[7] = dup_f32x2(xb.w);
#pragma unroll
            for (int r = 0; r < 8; r++) {
                fma_f32x2(acc[r][0], xp[r], w01.x);
                fma_f32x2(acc[r][1], xp[r], w01.y);
                fma_f32x2(acc[r][2], xp[r], w23.x);
                fma_f32x2(acc[r][3], xp[r], w23.y);
            }
        }
        __syncthreads();
    }

    if (GW2) {
        // ---- gate epilogue: gate[row] = sum_c relu(acc+gb1[c]) * gw2[c] ----
        float bout[8], w2v[8];
#pragma unroll
        for (int c = 0; c < 8; c++) {
            bout[c] = bias_out[tx8 + c];
            w2v[c] = GW2[tx8 + c];
        }
        float gb2v = gb2[0];
#pragma unroll
        for (int r = 0; r < 8; r++) {
            float o[8];
            o[0] = lo_f(acc[r][0]); o[1] = hi_f(acc[r][0]);
            o[2] = lo_f(acc[r][1]); o[3] = hi_f(acc[r][1]);
            o[4] = lo_f(acc[r][2]); o[5] = hi_f(acc[r][2]);
            o[6] = lo_f(acc[r][3]); o[7] = hi_f(acc[r][3]);
            float dot = 0.0f;
#pragma unroll
            for (int c = 0; c < 8; c++)
                dot += fmaxf(o[c] + bout[c], 0.0f) * w2v[c];
#pragma unroll
            for (int off = 1; off < 16; off <<= 1)
                dot += __shfl_xor_sync(0xFFFFFFFFu, dot, off);
            int row = row0 + ty8 + r;
            if (tx == 0 && row < n) {
                float gt = dot + gb2v;
                g_gate[row] = gt;
                atomicMax(&g_gmax[batch[row]], fkey(gt));
            }
        }
        return;
    }

    // ---- layer epilogue: Y = acc ; AGG = agg_bias + acc*dinv^2 ----
    float abv[8];
#pragma unroll
    for (int c = 0; c < 8; c++) abv[c] = agg_bias[tx8 + c];

#pragma unroll
    for (int r = 0; r < 8; r++) {
        int row = row0 + ty8 + r;
        if (row >= n) break;
        float o[8];
        o[0] = lo_f(acc[r][0]); o[1] = hi_f(acc[r][0]);
        o[2] = lo_f(acc[r][1]); o[3] = hi_f(acc[r][1]);
        o[4] = lo_f(acc[r][2]); o[5] = hi_f(acc[r][2]);
        o[6] = lo_f(acc[r][3]); o[7] = hi_f(acc[r][3]);
        float di = g_dinv[row];
        float w2 = di * di;
        *(float4*)(Y + (size_t)row * 128 + tx8) =
            make_float4(o[0], o[1], o[2], o[3]);
        *(float4*)(Y + (size_t)row * 128 + tx8 + 4) =
            make_float4(o[4], o[5], o[6], o[7]);
        float4 a0, a1;
        a0.x = abv[0] + o[0] * w2; a0.y = abv[1] + o[1] * w2;
        a0.z = abv[2] + o[2] * w2; a0.w = abv[3] + o[3] * w2;
        a1.x = abv[4] + o[4] * w2; a1.y = abv[5] + o[5] * w2;
        a1.z = abv[6] + o[6] * w2; a1.w = abv[7] + o[7] * w2;
        *(float4*)(AGG + (size_t)row * 128 + tx8)     = a0;
        *(float4*)(AGG + (size_t)row * 128 + tx8 + 4) = a1;
    }
}

// ---------------- init / degree / CSR build ----------------------------------
__global__ void k_init() {
    int i = blockIdx.x * blockDim.x + threadIdx.x;
    if (i < NN) g_cnt[i] = 0;
    if (i < GG) { g_gmax[i] = 0u; g_denom[i] = 0.0f; }
    if (i < GG * HH) g_pooled[i] = 0.0f;
}

__global__ void k_deg(const int* __restrict__ ei) {
    int i = blockIdx.x * blockDim.x + threadIdx.x;
    if (i < EE) atomicAdd(&g_cnt[ei[EE + i]], 1);
}

__global__ void k_dinv_fin() {
    int i = blockIdx.x * blockDim.x + threadIdx.x;
    if (i < NN) g_dinv[i] = rsqrtf((float)(g_cnt[i] + 1));   // +1 self loop
}

__global__ void k_scan1() {
    __shared__ int sh[256];
    int i = blockIdx.x * 256 + threadIdx.x;
    int v = (i < NN) ? g_cnt[i] : 0;
    sh[threadIdx.x] = v;
    __syncthreads();
    for (int off = 1; off < 256; off <<= 1) {
        int t = (threadIdx.x >= off) ? sh[threadIdx.x - off] : 0;
        __syncthreads();
        sh[threadIdx.x] += t;
        __syncthreads();
    }
    if (i < NN) g_off[i] = sh[threadIdx.x] - v;
    if (threadIdx.x == 255) g_bsum[blockIdx.x] = sh[255];
}

__global__ void k_scan2() {
    __shared__ int sh[256];
    int t = threadIdx.x;
    int v = (t < NB) ? g_bsum[t] : 0;
    sh[t] = v;
    __syncthreads();
    for (int off = 1; off < 256; off <<= 1) {
        int u = (t >= off) ? sh[t - off] : 0;
        __syncthreads();
        sh[t] += u;
        __syncthreads();
    }
    if (t < NB) g_boff[t] = sh[t] - v;
}

__global__ void k_scan3() {
    int i = blockIdx.x * 256 + threadIdx.x;
    if (i < NN) {
        int o = g_off[i] + g_boff[blockIdx.x];
        g_off[i] = o;
        g_pos[i] = o;
    }
    if (i == 0) g_off[NN] = EE;
}

__global__ void k_fill(const int* __restrict__ ei) {
    int e = blockIdx.x * blockDim.x + threadIdx.x;
    if (e >= EE) return;
    int d = ei[EE + e];
    int p = atomicAdd(&g_pos[d], 1);
    g_csr[p] = ei[e];
}

// ---------------- CSR gather + LayerNorm + ReLU (warp per dst node) -----------
// agg[d] starts at bias + h[d]*dinv[d]^2 (from GEMM epilogue); accumulate
// in-edges, then LN+ReLU in registers, write back.
__global__ void k_aggcsr(const float* __restrict__ h, float* __restrict__ agg,
                         const float* __restrict__ gamma,
                         const float* __restrict__ beta) {
    int node = blockIdx.x * 8 + (threadIdx.x >> 5);
    int lane = threadIdx.x & 31;
    if (node >= NN) return;

    float4 acc = ((const float4*)agg)[(size_t)node * 32 + lane];
    float4 acc2 = make_float4(0.f, 0.f, 0.f, 0.f);
    int e = g_off[node];
    const int end = g_off[node + 1];
    const float dd = g_dinv[node];

    for (; e + 1 < end; e += 2) {
        int s0 = g_csr[e];
        int s1 = g_csr[e + 1];
        float w0 = g_dinv[s0] * dd;
        float w1 = g_dinv[s1] * dd;
        float4 h0 = ((const float4*)h)[(size_t)s0 * 32 + lane];
        float4 h1 = ((const float4*)h)[(size_t)s1 * 32 + lane];
        acc.x += h0.x * w0;  acc.y += h0.y * w0;
        acc.z += h0.z * w0;  acc.w += h0.w * w0;
        acc2.x += h1.x * w1; acc2.y += h1.y * w1;
        acc2.z += h1.z * w1; acc2.w += h1.w * w1;
    }
    if (e < end) {
        int s0 = g_csr[e];
        float w0 = g_dinv[s0] * dd;
        float4 h0 = ((const float4*)h)[(size_t)s0 * 32 + lane];
        acc.x += h0.x * w0; acc.y += h0.y * w0;
        acc.z += h0.z * w0; acc.w += h0.w * w0;
    }
    acc.x += acc2.x; acc.y += acc2.y; acc.z += acc2.z; acc.w += acc2.w;

    // LayerNorm + ReLU
    float s = acc.x + acc.y + acc.z + acc.w;
#pragma unroll
    for (int off = 16; off; off >>= 1) s += __shfl_xor_sync(0xFFFFFFFFu, s, off);
    float m = s * (1.0f / 128.0f);
    float dx = acc.x - m, dy = acc.y - m, dz = acc.z - m, dw = acc.w - m;
    float q = dx * dx + dy * dy + dz * dz + dw * dw;
#pragma unroll
    for (int off = 16; off; off >>= 1) q += __shfl_xor_sync(0xFFFFFFFFu, q, off);
    float rinv = rsqrtf(q * (1.0f / 128.0f) + 1e-5f);
    float4 gv = ((const float4*)gamma)[lane];
    float4 bv = ((const float4*)beta)[lane];
    float4 o;
    o.x = fmaxf(dx * rinv * gv.x + bv.x, 0.f);
    o.y = fmaxf(dy * rinv * gv.y + bv.y, 0.f);
    o.z = fmaxf(dz * rinv * gv.z + bv.z, 0.f);
    o.w = fmaxf(dw * rinv * gv.w + bv.w, 0.f);
    ((float4*)agg)[(size_t)node * 32 + lane] = o;
}

// ---------------- softmax pieces ----------------------------------------------
__global__ void k_exp(const int* __restrict__ batch) {
    int i = blockIdx.x * blockDim.x + threadIdx.x;
    if (i >= NN) return;
    int g = batch[i];
    float a = expf(g_gate[i] - fdec(g_gmax[g]));
    g_expa[i] = a;
    atomicAdd(&g_denom[g], a);
}

__global__ void k_pool(const float* __restrict__ h, const int* __restrict__ batch) {
    int wid = (blockIdx.x * blockDim.x + threadIdx.x) >> 5;
    int lane = threadIdx.x & 31;
    if (wid >= NN) return;
    int g = batch[wid];
    float alpha = g_expa[wid] / g_denom[g];
    float4 v = ((const float4*)(h + (size_t)wid * 128))[lane];
    v.x *= alpha; v.y *= alpha; v.z *= alpha; v.w *= alpha;
    float* p = g_pooled + (size_t)g * 128 + lane * 4;
    asm volatile("red.global.add.v4.f32 [%0], {%1,%2,%3,%4};"
                 :: "l"(p), "f"(v.x), "f"(v.y), "f"(v.z), "f"(v.w) : "memory");
}

// ---------------- classifier --------------------------------------------------
__global__ void k_cls(const float* __restrict__ cw1, const float* __restrict__ cb1,
                      const float* __restrict__ cw2, const float* __restrict__ cb2,
                      float* __restrict__ out) {
    __shared__ float p[128];
    __shared__ float s0[128];
    __shared__ float s1[128];
    int g = blockIdx.x;
    int t = threadIdx.x;
    p[t] = g_pooled[(size_t)g * 128 + t];
    __syncthreads();
    float acc = cb1[t];
#pragma unroll 8
    for (int k = 0; k < 128; k++) acc += p[k] * cw1[k * 128 + t];
    acc = fmaxf(acc, 0.0f);
    s0[t] = acc * cw2[t * 2 + 0];
    s1[t] = acc * cw2[t * 2 + 1];
    __syncthreads();
    for (int off = 64; off; off >>= 1) {
        if (t < off) { s0[t] += s0[t + off]; s1[t] += s1[t + off]; }
        __syncthreads();
    }
    if (t == 0) {
        out[g * 2 + 0] = s0[0] + cb2[0];
        out[g * 2 + 1] = s1[0] + cb2[1];
    }
}

// ---------------- launch ------------------------------------------------------
extern "C" void kernel_launch(void* const* d_in, const int* in_sizes, int n_in,
                              void* d_out, int out_size) {
    const float* x      = (const float*)d_in[0];
    const int*   ei     = (const int*)  d_in[1];
    const int*   batch  = (const int*)  d_in[2];
    const float* W1     = (const float*)d_in[3];
    const float* b1     = (const float*)d_in[4];
    const float* ln1g   = (const float*)d_in[5];
    const float* ln1b   = (const float*)d_in[6];
    const float* W2     = (const float*)d_in[7];
    const float* b2     = (const float*)d_in[8];
    const float* ln2g   = (const float*)d_in[9];
    const float* ln2b   = (const float*)d_in[10];
    const float* gw1    = (const float*)d_in[11];
    const float* gb1    = (const float*)d_in[12];
    const float* gw2    = (const float*)d_in[13];
    const float* gb2    = (const float*)d_in[14];
    const float* cw1    = (const float*)d_in[15];
    const float* cb1    = (const float*)d_in[16];
    const float* cw2    = (const float*)d_in[17];
    const float* cb2    = (const float*)d_in[18];
    float* out = (float*)d_out;

    float* hbuf;   cudaGetSymbolAddress((void**)&hbuf, g_h);
    float* abuf;   cudaGetSymbolAddress((void**)&abuf, g_agg);

    const int T = 256;
    // ---- preprocessing: degree, dinv, CSR ----
    k_init<<<(GG * HH + T - 1) / T, T>>>();
    k_deg<<<(EE + T - 1) / T, T>>>(ei);
    k_dinv_fin<<<(NN + T - 1) / T, T>>>();
    k_scan1<<<NB, 256>>>();
    k_scan2<<<1, 256>>>();
    k_scan3<<<NB, 256>>>();
    k_fill<<<(EE + T - 1) / T, T>>>(ei);

    int gemm_blocks = (NN + 127) / 128;        // 391
    int agg_blocks  = (NN + 7) / 8;
    int warp_blocks = (NN * 32 + T - 1) / T;

    // ---- layer 1 ----
    k_gemm2<<<gemm_blocks, T>>>(x, W1, nullptr, b1, hbuf, abuf,
                                nullptr, nullptr, nullptr, NN);
    k_aggcsr<<<agg_blocks, T>>>(hbuf, abuf, ln1g, ln1b);

    // ---- layer 2 ----
    k_gemm2<<<gemm_blocks, T>>>(abuf, W2, nullptr, b2, hbuf, abuf,
                                nullptr, nullptr, nullptr, NN);
    k_aggcsr<<<agg_blocks, T>>>(hbuf, abuf, ln2g, ln2b);

    // ---- attention pooling (gate fused into GEMM epilogue) ----
    k_gemm2<<<gemm_blocks, T>>>(abuf, gw1, gb1, nullptr, nullptr, nullptr,
                                gw2, gb2, batch, NN);
    k_exp<<<(NN + T - 1) / T, T>>>(batch);
    k_pool<<<warp_blocks, T>>>(abuf, batch);

    // ---- classifier ----
    k_cls<<<GG, 128>>>(cw1, cb1, cw2, cb2, out);
}